// round 5
// baseline (speedup 1.0000x reference)
#include <cuda_runtime.h>
#include <stdint.h>

// Stable counting sort by tile_id (<=256 bins), scatter-minimized:
//  k_hist : tile id + per-block histogram + feature records (coalesced, padded 32B)
//  k_scan : per-bin exclusive scan across blocks -> g_baseB, tile_counts
//  k_off  : exclusive scan over bins -> tile_offsets
//  k_rank : stable warp ranks (registers); ONLY scattered op = 4B g_order[po]=p
//  k_emit : output-driven; coalesced g_order read, 1-sector g_feat gather,
//           shared-staged fully-coalesced feature writes.

#define NBIN    256
#define BLK     256
#define NW      8
#define ROUNDS  8
#define CHUNK   (BLK * ROUNDS)                    // 2048 pts per hist/rank block
#define MAXN    2000000
#define MAXBLK  ((MAXN + CHUNK - 1) / CHUNK)      // 977
#define ECHUNK  1024                              // output slots per emit block
#define EROUNDS (ECHUNK / BLK)                    // 4

__device__ unsigned char g_tile8[MAXN];
__device__ unsigned int  g_histB[NBIN * MAXBLK];
__device__ unsigned int  g_baseB[NBIN * MAXBLK];
__device__ int           g_counts [NBIN];
__device__ int           g_offsets[NBIN];
__device__ unsigned int  g_order[MAXN];
__device__ float4        g_feat[2 * MAXN];        // 32B padded record per point

// ------------- tile id + histogram + feature record (all coalesced) -------------
__global__ void __launch_bounds__(BLK) k_hist(const float2* __restrict__ pos,
                                              const float4* __restrict__ cov,
                                              const float* __restrict__ opac,
                                              const int* __restrict__ pnum,
                                              int N, int nblk) {
    __shared__ unsigned int cnt[NBIN];
    int tid = threadIdx.x;
    cnt[tid] = 0u;
    __syncthreads();
    int nt = *pnum;
    float ts = 1024.0f / (float)nt;
    int base = blockIdx.x * CHUNK;
    #pragma unroll
    for (int r = 0; r < ROUNDS; r++) {
        int p = base + r * BLK + tid;
        if (p < N) {
            float2 xy = pos[p];
            float4 cv = cov[p];
            float op  = opac[p];

            int tx = (int)floorf(xy.x / ts);
            int ty = (int)floorf(xy.y / ts);
            tx = min(max(tx, 0), nt - 1);
            ty = min(max(ty, 0), nt - 1);
            int k = ty * nt + tx;
            g_tile8[p] = (unsigned char)k;
            atomicAdd(&cnt[k], 1u);

            float a = cv.x, b = cv.y, c = cv.z, d = cv.w;
            float trace = a + d;
            float det   = a * d - b * c;
            float t1 = 0.5f * trace;
            float disc = trace * trace - 4.0f * det;
            float t2 = 0.5f * sqrtf(fmaxf(disc, 0.0f));
            float radius = fmaxf(t1 - t2, t1 + t2);
            float inv = 1.0f / det;

            g_feat[2 * p]     = make_float4(xy.x, xy.y, d * inv, -b * inv);
            g_feat[2 * p + 1] = make_float4(a * inv, op, radius, 0.0f);
        }
    }
    __syncthreads();
    g_histB[tid * nblk + blockIdx.x] = cnt[tid];
}

// ---------------- per-bin exclusive scan across blocks ----------------
__global__ void __launch_bounds__(BLK) k_scan(const int* __restrict__ pnum,
                                              int N, int nblk,
                                              float* __restrict__ out) {
    const int IT = 4;                      // nblk <= 1024
    int bin = blockIdx.x;
    int tid = threadIdx.x;
    int base = bin * nblk;
    unsigned int v[IT];
    unsigned int s = 0;
    #pragma unroll
    for (int j = 0; j < IT; j++) {
        int idx = tid * IT + j;
        v[j] = (idx < nblk) ? g_histB[base + idx] : 0u;
        s += v[j];
    }
    __shared__ unsigned int sh[BLK];
    sh[tid] = s;
    __syncthreads();
    for (int off = 1; off < BLK; off <<= 1) {
        unsigned int x = (tid >= off) ? sh[tid - off] : 0u;
        __syncthreads();
        sh[tid] += x;
        __syncthreads();
    }
    unsigned int run = sh[tid] - s;
    #pragma unroll
    for (int j = 0; j < IT; j++) {
        int idx = tid * IT + j;
        if (idx < nblk) g_baseB[base + idx] = run;
        run += v[j];
    }
    if (tid == BLK - 1) {
        g_counts[bin] = (int)sh[BLK - 1];
        int nt2 = (*pnum) * (*pnum);
        if (bin < nt2)
            out[7ull * (unsigned long long)N + bin] = (float)sh[BLK - 1];
    }
}

// ---------------- exclusive scan over bins -> tile_offsets ----------------
__global__ void __launch_bounds__(BLK) k_off(const int* __restrict__ pnum,
                                             int N, float* __restrict__ out) {
    int nt2 = (*pnum) * (*pnum);
    int tid = threadIdx.x;
    int v = (tid < nt2) ? g_counts[tid] : 0;
    __shared__ int sh[NBIN];
    sh[tid] = v;
    __syncthreads();
    for (int off = 1; off < BLK; off <<= 1) {
        int x = (tid >= off) ? sh[tid - off] : 0;
        __syncthreads();
        sh[tid] += x;
        __syncthreads();
    }
    int excl = sh[tid] - v;
    g_offsets[tid] = (tid < nt2) ? excl : 0;
    if (tid < nt2)
        out[7ull * (unsigned long long)N + nt2 + tid] = (float)excl;
}

// ---------------- stable rank (registers) -> scatter g_order only ----------------
__global__ void __launch_bounds__(BLK) k_rank(int N, int nblk) {
    __shared__ unsigned int wbase[NW * NBIN];   // counts -> absolute bases

    int tid  = threadIdx.x;
    int lane = tid & 31;
    int warp = tid >> 5;
    unsigned lt = (1u << lane) - 1u;
    int blk = blockIdx.x;
    int chunkStart = blk * CHUNK;
    const int WSEG = CHUNK / NW;

    #pragma unroll
    for (int i = 0; i < NW; i++) wbase[i * NBIN + tid] = 0u;
    __syncthreads();

    unsigned int* mycnt = &wbase[warp * NBIN];
    unsigned packed[ROUNDS];
    #pragma unroll
    for (int r = 0; r < ROUNDS; r++) {
        int local = warp * WSEG + r * 32 + lane;
        int p = chunkStart + local;
        int k = (p < N) ? (int)g_tile8[p] : 300;
        unsigned mask = __match_any_sync(0xffffffffu, k);
        int leader = __ffs(mask) - 1;
        int rank_w = __popc(mask & lt);
        unsigned base = 0u;
        if (lane == leader && k < 256) {
            base = mycnt[k];
            mycnt[k] = base + (unsigned)__popc(mask);
        }
        base = __shfl_sync(0xffffffffu, base, leader);
        packed[r] = ((base + (unsigned)rank_w) << 16) | (unsigned)(k & 0xff);
    }
    __syncthreads();

    {   // absolute base per (warp,bin)
        unsigned s = (unsigned)g_offsets[tid] + g_baseB[tid * nblk + blk];
        #pragma unroll
        for (int w = 0; w < NW; w++) {
            unsigned c = wbase[w * NBIN + tid];
            wbase[w * NBIN + tid] = s;
            s += c;
        }
    }
    __syncthreads();

    const unsigned int* mybase = &wbase[warp * NBIN];
    #pragma unroll
    for (int r = 0; r < ROUNDS; r++) {
        int local = warp * WSEG + r * 32 + lane;
        int p = chunkStart + local;
        if (p < N) {
            int k = (int)(packed[r] & 0xffu);
            unsigned po = mybase[k] + (packed[r] >> 16);
            g_order[po] = (unsigned)p;          // ONLY scattered store (4B)
        }
    }
}

// ---------------- output-driven emit: gather 1 sector, write coalesced ----------------
__global__ void __launch_bounds__(BLK) k_emit(const int* __restrict__ pnum,
                                              int N, float* __restrict__ out) {
    __shared__ float stage[ECHUNK * 7];         // 28KB, stride-7 = conflict-free

    int tid = threadIdx.x;
    int base = blockIdx.x * ECHUNK;
    int valid = min(ECHUNK, N - base);
    int nt2 = (*pnum) * (*pnum);
    unsigned long long orderBase =
        7ull * (unsigned long long)N + 2ull * (unsigned long long)nt2;

    #pragma unroll
    for (int r = 0; r < EROUNDS; r++) {
        int j = r * BLK + tid;
        int jg = base + j;
        if (jg < N) {
            unsigned p = g_order[jg];
            float4 A = g_feat[2 * p];
            float4 B = g_feat[2 * p + 1];
            float* s = &stage[j * 7];
            s[0] = A.x; s[1] = A.y; s[2] = A.z; s[3] = A.w;
            s[4] = B.x; s[5] = B.y; s[6] = B.z;
            out[orderBase + jg] = (float)p;     // coalesced
        }
    }
    __syncthreads();

    if (valid == ECHUNK) {
        const float4* s4 = (const float4*)stage;
        float4* o4 = (float4*)(out + (unsigned long long)base * 7ull);
        #pragma unroll
        for (int i = 0; i < (ECHUNK * 7 / 4) / BLK; i++)
            o4[i * BLK + tid] = s4[i * BLK + tid];
    } else if (valid > 0) {
        float* o = out + (unsigned long long)base * 7ull;
        for (int i = tid; i < valid * 7; i += BLK)
            o[i] = stage[i];
    }
}

extern "C" void kernel_launch(void* const* d_in, const int* in_sizes, int n_in,
                              void* d_out, int out_size) {
    const float2* pos  = (const float2*)d_in[0];
    const float4* cov  = (const float4*)d_in[1];
    const float*  op   = (const float*)d_in[2];
    const int*    pnum = (const int*)d_in[3];
    int N = in_sizes[0] / 2;
    int nblk  = (N + CHUNK - 1) / CHUNK;
    int eblk  = (N + ECHUNK - 1) / ECHUNK;
    float* out = (float*)d_out;

    k_hist<<<nblk, BLK>>>(pos, cov, op, pnum, N, nblk);
    k_scan<<<NBIN, BLK>>>(pnum, N, nblk, out);
    k_off <<<1,    BLK>>>(pnum, N, out);
    k_rank<<<nblk, BLK>>>(N, nblk);
    k_emit<<<eblk, BLK>>>(pnum, N, out);
}

// round 6
// speedup vs baseline: 1.4394x; 1.4394x over previous
#include <cuda_runtime.h>
#include <stdint.h>

// Stable counting sort by tile_id (<=256 bins), permutation = one 32B sector/point:
//  k_hist : tile id (1B) + per-block 256-bin histogram (reads pos only)
//  k_scan : per-bin exclusive scan across blocks -> g_baseB, tile_counts
//  k_off  : exclusive scan over bins -> tile_offsets
//  k_sort : stable warp ranks (registers) + coalesced input reads + feature math,
//           scatter ONE aligned 32B record (feat7 + order) as 2x STG.128
//  k_emit : pure streaming: coalesced read of g_sorted, shared-staged 32B->28B
//           compaction, coalesced feat + order writes.

#define NBIN    256
#define BLK     256
#define NW      8
#define ROUNDS  8
#define CHUNK   (BLK * ROUNDS)                    // 2048 pts per block
#define MAXN    2000000
#define MAXBLK  ((MAXN + CHUNK - 1) / CHUNK)      // 977
#define ECHUNK  1024
#define EROUNDS (ECHUNK / BLK)                    // 4

__device__ unsigned char g_tile8[MAXN];
__device__ unsigned int  g_histB[NBIN * MAXBLK];
__device__ unsigned int  g_baseB[NBIN * MAXBLK];
__device__ int           g_counts [NBIN];
__device__ int           g_offsets[NBIN];
__device__ float4        g_sorted[2 * MAXN];      // 32B record per OUTPUT slot

// ---------------- tile id + per-block histogram ----------------
__global__ void __launch_bounds__(BLK) k_hist(const float2* __restrict__ pos,
                                              const int* __restrict__ pnum,
                                              int N, int nblk) {
    __shared__ unsigned int cnt[NBIN];
    int tid = threadIdx.x;
    cnt[tid] = 0u;
    __syncthreads();
    int nt = *pnum;
    float ts = 1024.0f / (float)nt;
    int base = blockIdx.x * CHUNK;
    #pragma unroll
    for (int r = 0; r < ROUNDS; r++) {
        int p = base + r * BLK + tid;
        if (p < N) {
            float2 xy = pos[p];
            int tx = (int)floorf(xy.x / ts);
            int ty = (int)floorf(xy.y / ts);
            tx = min(max(tx, 0), nt - 1);
            ty = min(max(ty, 0), nt - 1);
            int k = ty * nt + tx;
            g_tile8[p] = (unsigned char)k;
            atomicAdd(&cnt[k], 1u);
        }
    }
    __syncthreads();
    g_histB[tid * nblk + blockIdx.x] = cnt[tid];
}

// ---------------- per-bin exclusive scan across blocks ----------------
__global__ void __launch_bounds__(BLK) k_scan(const int* __restrict__ pnum,
                                              int N, int nblk,
                                              float* __restrict__ out) {
    const int IT = 4;                      // nblk <= 1024
    int bin = blockIdx.x;
    int tid = threadIdx.x;
    int base = bin * nblk;
    unsigned int v[IT];
    unsigned int s = 0;
    #pragma unroll
    for (int j = 0; j < IT; j++) {
        int idx = tid * IT + j;
        v[j] = (idx < nblk) ? g_histB[base + idx] : 0u;
        s += v[j];
    }
    __shared__ unsigned int sh[BLK];
    sh[tid] = s;
    __syncthreads();
    for (int off = 1; off < BLK; off <<= 1) {
        unsigned int x = (tid >= off) ? sh[tid - off] : 0u;
        __syncthreads();
        sh[tid] += x;
        __syncthreads();
    }
    unsigned int run = sh[tid] - s;
    #pragma unroll
    for (int j = 0; j < IT; j++) {
        int idx = tid * IT + j;
        if (idx < nblk) g_baseB[base + idx] = run;
        run += v[j];
    }
    if (tid == BLK - 1) {
        g_counts[bin] = (int)sh[BLK - 1];
        int nt2 = (*pnum) * (*pnum);
        if (bin < nt2)
            out[7ull * (unsigned long long)N + bin] = (float)sh[BLK - 1];
    }
}

// ---------------- exclusive scan over bins -> tile_offsets ----------------
__global__ void __launch_bounds__(BLK) k_off(const int* __restrict__ pnum,
                                             int N, float* __restrict__ out) {
    int nt2 = (*pnum) * (*pnum);
    int tid = threadIdx.x;
    int v = (tid < nt2) ? g_counts[tid] : 0;
    __shared__ int sh[NBIN];
    sh[tid] = v;
    __syncthreads();
    for (int off = 1; off < BLK; off <<= 1) {
        int x = (tid >= off) ? sh[tid - off] : 0;
        __syncthreads();
        sh[tid] += x;
        __syncthreads();
    }
    int excl = sh[tid] - v;
    g_offsets[tid] = (tid < nt2) ? excl : 0;
    if (tid < nt2)
        out[7ull * (unsigned long long)N + nt2 + tid] = (float)excl;
}

// ------- stable rank + feature math + single-sector 32B record scatter -------
__global__ void __launch_bounds__(BLK) k_sort(
    const float2* __restrict__ pos, const float4* __restrict__ cov,
    const float* __restrict__ opac, int N, int nblk)
{
    __shared__ unsigned int wbase[NW * NBIN];

    int tid  = threadIdx.x;
    int lane = tid & 31;
    int warp = tid >> 5;
    unsigned lt = (1u << lane) - 1u;
    int blk = blockIdx.x;
    int chunkStart = blk * CHUNK;
    const int WSEG = CHUNK / NW;

    #pragma unroll
    for (int i = 0; i < NW; i++) wbase[i * NBIN + tid] = 0u;
    __syncthreads();

    // Phase A: stable within-warp ranks (registers)
    unsigned int* mycnt = &wbase[warp * NBIN];
    unsigned packed[ROUNDS];
    #pragma unroll
    for (int r = 0; r < ROUNDS; r++) {
        int local = warp * WSEG + r * 32 + lane;
        int p = chunkStart + local;
        int k = (p < N) ? (int)g_tile8[p] : 300;
        unsigned mask = __match_any_sync(0xffffffffu, k);
        int leader = __ffs(mask) - 1;
        int rank_w = __popc(mask & lt);
        unsigned base = 0u;
        if (lane == leader && k < 256) {
            base = mycnt[k];
            mycnt[k] = base + (unsigned)__popc(mask);
        }
        base = __shfl_sync(0xffffffffu, base, leader);
        packed[r] = ((base + (unsigned)rank_w) << 16) | (unsigned)(k & 0xff);
    }
    __syncthreads();

    // Combine: absolute base per (warp,bin)
    {
        unsigned s = (unsigned)g_offsets[tid] + g_baseB[tid * nblk + blk];
        #pragma unroll
        for (int w = 0; w < NW; w++) {
            unsigned c = wbase[w * NBIN + tid];
            wbase[w * NBIN + tid] = s;
            s += c;
        }
    }
    __syncthreads();

    // Phase C: coalesced reads + math, scatter one aligned 32B record (2x STG.128)
    const unsigned int* mybase = &wbase[warp * NBIN];
    #pragma unroll
    for (int r = 0; r < ROUNDS; r++) {
        int local = warp * WSEG + r * 32 + lane;
        int p = chunkStart + local;
        if (p < N) {
            int k = (int)(packed[r] & 0xffu);
            unsigned po = mybase[k] + (packed[r] >> 16);

            float2 xy = pos[p];
            float4 cv = cov[p];
            float op  = opac[p];
            float a = cv.x, b = cv.y, c = cv.z, d = cv.w;
            float trace = a + d;
            float det   = a * d - b * c;
            float t1 = 0.5f * trace;
            float disc = trace * trace - 4.0f * det;
            float t2 = 0.5f * sqrtf(fmaxf(disc, 0.0f));
            float radius = fmaxf(t1 - t2, t1 + t2);
            float inv = 1.0f / det;

            g_sorted[2 * po]     = make_float4(xy.x, xy.y, d * inv, -b * inv);
            g_sorted[2 * po + 1] = make_float4(a * inv, op, radius, (float)p);
        }
    }
}

// ---------------- pure streaming emit: 32B -> 28B + order ----------------
__global__ void __launch_bounds__(BLK) k_emit(const int* __restrict__ pnum,
                                              int N, float* __restrict__ out) {
    __shared__ float stage[ECHUNK * 7];         // 28KB

    int tid = threadIdx.x;
    int base = blockIdx.x * ECHUNK;
    int valid = min(ECHUNK, N - base);
    int nt2 = (*pnum) * (*pnum);
    unsigned long long orderBase =
        7ull * (unsigned long long)N + 2ull * (unsigned long long)nt2;

    #pragma unroll
    for (int r = 0; r < EROUNDS; r++) {
        int j = r * BLK + tid;
        int jg = base + j;
        if (jg < N) {
            float4 A = g_sorted[2 * jg];        // coalesced
            float4 B = g_sorted[2 * jg + 1];
            float* s = &stage[j * 7];
            s[0] = A.x; s[1] = A.y; s[2] = A.z; s[3] = A.w;
            s[4] = B.x; s[5] = B.y; s[6] = B.z;
            out[orderBase + jg] = B.w;          // coalesced order write
        }
    }
    __syncthreads();

    if (valid == ECHUNK) {
        const float4* s4 = (const float4*)stage;
        float4* o4 = (float4*)(out + (unsigned long long)base * 7ull);
        #pragma unroll
        for (int i = 0; i < (ECHUNK * 7 / 4) / BLK; i++)
            o4[i * BLK + tid] = s4[i * BLK + tid];
    } else if (valid > 0) {
        float* o = out + (unsigned long long)base * 7ull;
        for (int i = tid; i < valid * 7; i += BLK)
            o[i] = stage[i];
    }
}

extern "C" void kernel_launch(void* const* d_in, const int* in_sizes, int n_in,
                              void* d_out, int out_size) {
    const float2* pos  = (const float2*)d_in[0];
    const float4* cov  = (const float4*)d_in[1];
    const float*  op   = (const float*)d_in[2];
    const int*    pnum = (const int*)d_in[3];
    int N = in_sizes[0] / 2;
    int nblk = (N + CHUNK - 1) / CHUNK;
    int eblk = (N + ECHUNK - 1) / ECHUNK;
    float* out = (float*)d_out;

    k_hist<<<nblk, BLK>>>(pos, pnum, N, nblk);
    k_scan<<<NBIN, BLK>>>(pnum, N, nblk, out);
    k_off <<<1,    BLK>>>(pnum, N, out);
    k_sort<<<nblk, BLK>>>(pos, cov, op, N, nblk);
    k_emit<<<eblk, BLK>>>(pnum, N, out);
}

// round 7
// speedup vs baseline: 1.9002x; 1.3201x over previous
#include <cuda_runtime.h>
#include <stdint.h>

// Stable counting sort by tile_id (<=256 bins), direct-to-output:
//  k_hist : tile id (1B) + per-block 256-bin histogram
//  k_scan : per-bin exclusive scan across blocks -> g_baseB, tile_counts
//  k_off  : exclusive scan over bins -> tile_offsets
//  k_sort : stable warp ranks (registers) -> stage chunk LOCALLY SORTED in shared
//           (SoA planes) + per-slot global dest index; flush straight to out with
//           run-coalesced flat copies. No intermediate global staging, no emit.

#define NBIN    256
#define BLK     256
#define NW      8
#define ROUNDS  4
#define WSEG    (ROUNDS * 32)                     // 128 pts per warp
#define CHUNK   (NW * WSEG)                       // 1024 pts per block
#define PITCH   (CHUNK + 1)                       // bank-spread plane pitch
#define MAXN    2000000
#define MAXBLK  ((MAXN + CHUNK - 1) / CHUNK)      // 1954

__device__ unsigned char g_tile8[MAXN];
__device__ unsigned int  g_histB[NBIN * MAXBLK];
__device__ unsigned int  g_baseB[NBIN * MAXBLK];
__device__ int           g_counts [NBIN];
__device__ int           g_offsets[NBIN];

// ---------------- tile id + per-block histogram ----------------
__global__ void __launch_bounds__(BLK) k_hist(const float2* __restrict__ pos,
                                              const int* __restrict__ pnum,
                                              int N, int nblk) {
    __shared__ unsigned int cnt[NBIN];
    int tid = threadIdx.x;
    cnt[tid] = 0u;
    __syncthreads();
    int nt = *pnum;
    float ts = 1024.0f / (float)nt;
    int base = blockIdx.x * CHUNK;
    #pragma unroll
    for (int r = 0; r < ROUNDS; r++) {
        int p = base + r * BLK + tid;
        if (p < N) {
            float2 xy = pos[p];
            int tx = (int)floorf(xy.x / ts);
            int ty = (int)floorf(xy.y / ts);
            tx = min(max(tx, 0), nt - 1);
            ty = min(max(ty, 0), nt - 1);
            int k = ty * nt + tx;
            g_tile8[p] = (unsigned char)k;
            atomicAdd(&cnt[k], 1u);
        }
    }
    __syncthreads();
    g_histB[tid * nblk + blockIdx.x] = cnt[tid];
}

// ---------------- per-bin exclusive scan across blocks ----------------
__global__ void __launch_bounds__(BLK) k_scan(const int* __restrict__ pnum,
                                              int N, int nblk,
                                              float* __restrict__ out) {
    const int IT = 8;                      // nblk <= 2048
    int bin = blockIdx.x;
    int tid = threadIdx.x;
    int base = bin * nblk;
    unsigned int v[IT];
    unsigned int s = 0;
    #pragma unroll
    for (int j = 0; j < IT; j++) {
        int idx = tid * IT + j;
        v[j] = (idx < nblk) ? g_histB[base + idx] : 0u;
        s += v[j];
    }
    __shared__ unsigned int sh[BLK];
    sh[tid] = s;
    __syncthreads();
    for (int off = 1; off < BLK; off <<= 1) {
        unsigned int x = (tid >= off) ? sh[tid - off] : 0u;
        __syncthreads();
        sh[tid] += x;
        __syncthreads();
    }
    unsigned int run = sh[tid] - s;
    #pragma unroll
    for (int j = 0; j < IT; j++) {
        int idx = tid * IT + j;
        if (idx < nblk) g_baseB[base + idx] = run;
        run += v[j];
    }
    if (tid == BLK - 1) {
        g_counts[bin] = (int)sh[BLK - 1];
        int nt2 = (*pnum) * (*pnum);
        if (bin < nt2)
            out[7ull * (unsigned long long)N + bin] = (float)sh[BLK - 1];
    }
}

// ---------------- exclusive scan over bins -> tile_offsets ----------------
__global__ void __launch_bounds__(BLK) k_off(const int* __restrict__ pnum,
                                             int N, float* __restrict__ out) {
    int nt2 = (*pnum) * (*pnum);
    int tid = threadIdx.x;
    int v = (tid < nt2) ? g_counts[tid] : 0;
    __shared__ int sh[NBIN];
    sh[tid] = v;
    __syncthreads();
    for (int off = 1; off < BLK; off <<= 1) {
        int x = (tid >= off) ? sh[tid - off] : 0;
        __syncthreads();
        sh[tid] += x;
        __syncthreads();
    }
    int excl = sh[tid] - v;
    g_offsets[tid] = (tid < nt2) ? excl : 0;
    if (tid < nt2)
        out[7ull * (unsigned long long)N + nt2 + tid] = (float)excl;
}

// ------- rank + feature math + local-sort staging + run-coalesced output -------
__global__ void __launch_bounds__(BLK) k_sort(
    const float2* __restrict__ pos, const float4* __restrict__ cov,
    const float* __restrict__ opac, const int* __restrict__ pnum,
    int N, int nblk, float* __restrict__ out)
{
    __shared__ float          stage[8 * PITCH];     // ~32.8KB SoA planes (7 feat + p)
    __shared__ unsigned int   gdst[CHUNK];          // 4KB  global record idx per slot
    __shared__ unsigned short wcnt[NW * NBIN];      // 4KB  counters -> warp prefix
    __shared__ unsigned short sbinstart[NBIN];      // 0.5KB local bin starts
    __shared__ int            adj[NBIN];            // 1KB  global base - local start
    __shared__ unsigned int   scanbuf[NBIN];        // 1KB

    int tid  = threadIdx.x;
    int lane = tid & 31;
    int warp = tid >> 5;
    unsigned lt = (1u << lane) - 1u;
    int blk = blockIdx.x;
    int chunkStart = blk * CHUNK;
    int valid = min(CHUNK, N - chunkStart);

    // zero counters (NW*NBIN u16 = 1024 u32)
    #pragma unroll
    for (int i = 0; i < NW * NBIN / 2 / BLK; i++)
        ((uint32_t*)wcnt)[i * BLK + tid] = 0u;
    __syncthreads();

    // Phase A: stable within-warp ranks (registers)
    unsigned short* mycnt = &wcnt[warp * NBIN];
    unsigned packed[ROUNDS];
    #pragma unroll
    for (int r = 0; r < ROUNDS; r++) {
        int local = warp * WSEG + r * 32 + lane;
        int p = chunkStart + local;
        int k = (p < N) ? (int)g_tile8[p] : 300;
        unsigned mask = __match_any_sync(0xffffffffu, k);
        int leader = __ffs(mask) - 1;
        int rank_w = __popc(mask & lt);
        unsigned base = 0u;
        if (lane == leader && k < 256) {
            base = (unsigned)mycnt[k];
            mycnt[k] = (unsigned short)(base + (unsigned)__popc(mask));
        }
        base = __shfl_sync(0xffffffffu, base, leader);
        packed[r] = ((base + (unsigned)rank_w) << 16) | (unsigned)(k & 0xffff);
    }
    __syncthreads();

    // Combine: warp prefix per bin (in place), block bin totals, local starts, adj
    {
        unsigned s = 0u;
        #pragma unroll
        for (int w = 0; w < NW; w++) {
            unsigned c = (unsigned)wcnt[w * NBIN + tid];
            wcnt[w * NBIN + tid] = (unsigned short)s;
            s += c;
        }
        scanbuf[tid] = s;
        __syncthreads();
        unsigned v = s;
        for (int off = 1; off < NBIN; off <<= 1) {
            unsigned x = (tid >= off) ? scanbuf[tid - off] : 0u;
            __syncthreads();
            scanbuf[tid] += x;
            __syncthreads();
        }
        unsigned bs = scanbuf[tid] - v;            // exclusive local start
        sbinstart[tid] = (unsigned short)bs;
        adj[tid] = (int)((unsigned)g_offsets[tid] + g_baseB[tid * nblk + blk]) - (int)bs;
    }
    __syncthreads();

    // Phase C: coalesced reads + math -> stage at locally-sorted slot
    #pragma unroll
    for (int r = 0; r < ROUNDS; r++) {
        int local = warp * WSEG + r * 32 + lane;
        int p = chunkStart + local;
        if (p < N) {
            int k = (int)(packed[r] & 0xffffu);
            int slot = (int)sbinstart[k] + (int)mycnt[k] + (int)(packed[r] >> 16);

            float2 xy = pos[p];
            float4 cv = cov[p];
            float op  = opac[p];
            float a = cv.x, b = cv.y, c = cv.z, d = cv.w;
            float trace = a + d;
            float det   = a * d - b * c;
            float t1 = 0.5f * trace;
            float disc = trace * trace - 4.0f * det;
            float t2 = 0.5f * sqrtf(fmaxf(disc, 0.0f));
            float radius = fmaxf(t1 - t2, t1 + t2);
            float inv = 1.0f / det;

            stage[0 * PITCH + slot] = xy.x;
            stage[1 * PITCH + slot] = xy.y;
            stage[2 * PITCH + slot] = d * inv;
            stage[3 * PITCH + slot] = -b * inv;
            stage[4 * PITCH + slot] = a * inv;
            stage[5 * PITCH + slot] = op;
            stage[6 * PITCH + slot] = radius;
            stage[7 * PITCH + slot] = (float)p;
            gdst[slot] = (unsigned)(adj[k] + slot);
        }
    }
    __syncthreads();

    // Flush: run-coalesced flat copies (addr = const + i within each bin run)
    int nt2 = (*pnum) * (*pnum);
    unsigned long long orderBase =
        7ull * (unsigned long long)N + 2ull * (unsigned long long)nt2;
    int totF = valid * 7;
    for (int i = tid; i < totF; i += BLK) {
        int j = i / 7;
        int c = i - 7 * j;
        out[(unsigned long long)gdst[j] * 7ull + c] = stage[c * PITCH + j];
    }
    for (int i = tid; i < valid; i += BLK) {
        out[orderBase + gdst[i]] = stage[7 * PITCH + i];
    }
}

extern "C" void kernel_launch(void* const* d_in, const int* in_sizes, int n_in,
                              void* d_out, int out_size) {
    const float2* pos  = (const float2*)d_in[0];
    const float4* cov  = (const float4*)d_in[1];
    const float*  op   = (const float*)d_in[2];
    const int*    pnum = (const int*)d_in[3];
    int N = in_sizes[0] / 2;
    int nblk = (N + CHUNK - 1) / CHUNK;
    float* out = (float*)d_out;

    k_hist<<<nblk, BLK>>>(pos, pnum, N, nblk);
    k_scan<<<NBIN, BLK>>>(pnum, N, nblk, out);
    k_off <<<1,    BLK>>>(pnum, N, out);
    k_sort<<<nblk, BLK>>>(pos, cov, op, pnum, N, nblk, out);
}

// round 8
// speedup vs baseline: 2.0808x; 1.0951x over previous
#include <cuda_runtime.h>
#include <stdint.h>

// Stable counting sort by tile_id (<=256 bins), direct-to-output:
//  k_hist : tile id (1B) + per-block 256-bin histogram
//  k_scan : per-bin exclusive scan across blocks -> g_baseB, g_counts, tile_counts
//  k_sort : stable warp ranks (registers) -> chunk staged LOCALLY SORTED in shared
//           (SoA planes, conflict-minimized pitch); packed u64 shuffle-scan computes
//           BOTH local bin starts and global tile_offsets (k_off fused away);
//           run-coalesced flat flush straight to out.

#define NBIN    256
#define BLK     256
#define NW      8
#define ROUNDS  4
#define WSEG    (ROUNDS * 32)                     // 128 pts per warp
#define CHUNK   (NW * WSEG)                       // 1024 pts per block
#define PITCH   (CHUNK + 5)                       // pitch%32==5 -> ~conflict-free flush
#define MAXN    2000000
#define MAXBLK  ((MAXN + CHUNK - 1) / CHUNK)      // 1954

__device__ unsigned char g_tile8[MAXN];
__device__ unsigned int  g_histB[NBIN * MAXBLK];
__device__ unsigned int  g_baseB[NBIN * MAXBLK];
__device__ unsigned int  g_counts[NBIN];

// ---------------- tile id + per-block histogram ----------------
__global__ void __launch_bounds__(BLK) k_hist(const float2* __restrict__ pos,
                                              const int* __restrict__ pnum,
                                              int N, int nblk) {
    __shared__ unsigned int cnt[NBIN];
    int tid = threadIdx.x;
    cnt[tid] = 0u;
    __syncthreads();
    int nt = *pnum;
    float ts = 1024.0f / (float)nt;
    int base = blockIdx.x * CHUNK;
    #pragma unroll
    for (int r = 0; r < ROUNDS; r++) {
        int p = base + r * BLK + tid;
        if (p < N) {
            float2 xy = pos[p];
            int tx = (int)floorf(xy.x / ts);
            int ty = (int)floorf(xy.y / ts);
            tx = min(max(tx, 0), nt - 1);
            ty = min(max(ty, 0), nt - 1);
            int k = ty * nt + tx;
            g_tile8[p] = (unsigned char)k;
            atomicAdd(&cnt[k], 1u);
        }
    }
    __syncthreads();
    g_histB[tid * nblk + blockIdx.x] = cnt[tid];
}

// ---------------- per-bin exclusive scan across blocks ----------------
__global__ void __launch_bounds__(BLK) k_scan(const int* __restrict__ pnum,
                                              int N, int nblk,
                                              float* __restrict__ out) {
    const int IT = 8;                      // nblk <= 2048
    int bin = blockIdx.x;
    int tid = threadIdx.x;
    int base = bin * nblk;
    unsigned int v[IT];
    unsigned int s = 0;
    #pragma unroll
    for (int j = 0; j < IT; j++) {
        int idx = tid * IT + j;
        v[j] = (idx < nblk) ? g_histB[base + idx] : 0u;
        s += v[j];
    }
    __shared__ unsigned int sh[BLK];
    sh[tid] = s;
    __syncthreads();
    for (int off = 1; off < BLK; off <<= 1) {
        unsigned int x = (tid >= off) ? sh[tid - off] : 0u;
        __syncthreads();
        sh[tid] += x;
        __syncthreads();
    }
    unsigned int run = sh[tid] - s;
    #pragma unroll
    for (int j = 0; j < IT; j++) {
        int idx = tid * IT + j;
        if (idx < nblk) g_baseB[base + idx] = run;
        run += v[j];
    }
    if (tid == BLK - 1) {
        g_counts[bin] = sh[BLK - 1];
        int nt2 = (*pnum) * (*pnum);
        if (bin < nt2)
            out[7ull * (unsigned long long)N + bin] = (float)sh[BLK - 1];
    }
}

// ------- rank + feature math + local-sort staging + run-coalesced output -------
__global__ void __launch_bounds__(BLK) k_sort(
    const float2* __restrict__ pos, const float4* __restrict__ cov,
    const float* __restrict__ opac, const int* __restrict__ pnum,
    int N, int nblk, float* __restrict__ out)
{
    __shared__ float          stage[8 * PITCH];     // ~33KB SoA planes (7 feat + p)
    __shared__ unsigned int   gdst[CHUNK];          // 4KB global record idx per slot
    __shared__ unsigned short wcnt[NW * NBIN];      // 4KB counters -> warp prefix
    __shared__ unsigned short sbinstart[NBIN];      // local bin starts
    __shared__ int            adj[NBIN];            // global base - local start
    __shared__ unsigned long long wsum[NW];

    int tid  = threadIdx.x;
    int lane = tid & 31;
    int warp = tid >> 5;
    unsigned lt = (1u << lane) - 1u;
    int blk = blockIdx.x;
    int chunkStart = blk * CHUNK;
    int valid = min(CHUNK, N - chunkStart);
    int nt2;
    {
        int nt = *pnum;
        nt2 = nt * nt;
    }

    #pragma unroll
    for (int i = 0; i < NW * NBIN / 2 / BLK; i++)
        ((uint32_t*)wcnt)[i * BLK + tid] = 0u;
    __syncthreads();

    // Phase A: stable within-warp ranks (registers)
    unsigned short* mycnt = &wcnt[warp * NBIN];
    unsigned packed[ROUNDS];
    #pragma unroll
    for (int r = 0; r < ROUNDS; r++) {
        int local = warp * WSEG + r * 32 + lane;
        int p = chunkStart + local;
        int k = (p < N) ? (int)g_tile8[p] : 300;
        unsigned mask = __match_any_sync(0xffffffffu, k);
        int leader = __ffs(mask) - 1;
        int rank_w = __popc(mask & lt);
        unsigned base = 0u;
        if (lane == leader && k < 256) {
            base = (unsigned)mycnt[k];
            mycnt[k] = (unsigned short)(base + (unsigned)__popc(mask));
        }
        base = __shfl_sync(0xffffffffu, base, leader);
        packed[r] = ((base + (unsigned)rank_w) << 16) | (unsigned)(k & 0xffff);
    }
    __syncthreads();

    // Combine: in-place warp prefix per bin; then ONE packed u64 shuffle-scan over
    // bins computing simultaneously: lo = exscan(g_counts) = tile_offsets,
    //                                hi = exscan(local bin totals) = local starts.
    unsigned loc;
    {
        unsigned s = 0u;
        #pragma unroll
        for (int w = 0; w < NW; w++) {
            unsigned c = (unsigned)wcnt[w * NBIN + tid];
            wcnt[w * NBIN + tid] = (unsigned short)s;
            s += c;
        }
        loc = s;
    }
    unsigned cntg = g_counts[tid];
    unsigned long long v64 = ((unsigned long long)loc << 32) | (unsigned long long)cntg;
    unsigned long long x = v64;
    #pragma unroll
    for (int d = 1; d < 32; d <<= 1) {
        unsigned long long y = __shfl_up_sync(0xffffffffu, x, d);
        if (lane >= d) x += y;
    }
    if (lane == 31) wsum[warp] = x;
    __syncthreads();
    if (warp == 0) {
        unsigned long long t = (lane < NW) ? wsum[lane] : 0ull;
        #pragma unroll
        for (int d = 1; d < NW; d <<= 1) {
            unsigned long long y = __shfl_up_sync(0xffffffffu, t, d);
            if (lane >= d) t += y;
        }
        if (lane < NW) wsum[lane] = t;
    }
    __syncthreads();
    {
        unsigned long long incl = x + (warp ? wsum[warp - 1] : 0ull);
        unsigned long long excl = incl - v64;
        unsigned offs = (unsigned)excl;          // tile_offsets[tid]
        unsigned bs   = (unsigned)(excl >> 32);  // local start
        sbinstart[tid] = (unsigned short)bs;
        adj[tid] = (int)(offs + g_baseB[tid * nblk + blk]) - (int)bs;
        if (blk == 0 && tid < nt2)
            out[7ull * (unsigned long long)N + nt2 + tid] = (float)offs;
    }
    __syncthreads();

    // Phase C: coalesced reads + math -> stage at locally-sorted slot
    #pragma unroll
    for (int r = 0; r < ROUNDS; r++) {
        int local = warp * WSEG + r * 32 + lane;
        int p = chunkStart + local;
        if (p < N) {
            int k = (int)(packed[r] & 0xffffu);
            int slot = (int)sbinstart[k] + (int)mycnt[k] + (int)(packed[r] >> 16);

            float2 xy = pos[p];
            float4 cv = cov[p];
            float op  = opac[p];
            float a = cv.x, b = cv.y, c = cv.z, d = cv.w;
            float trace = a + d;
            float det   = a * d - b * c;
            float t1 = 0.5f * trace;
            float disc = trace * trace - 4.0f * det;
            float t2 = 0.5f * sqrtf(fmaxf(disc, 0.0f));
            float radius = fmaxf(t1 - t2, t1 + t2);
            float inv = 1.0f / det;

            stage[0 * PITCH + slot] = xy.x;
            stage[1 * PITCH + slot] = xy.y;
            stage[2 * PITCH + slot] = d * inv;
            stage[3 * PITCH + slot] = -b * inv;
            stage[4 * PITCH + slot] = a * inv;
            stage[5 * PITCH + slot] = op;
            stage[6 * PITCH + slot] = radius;
            stage[7 * PITCH + slot] = (float)p;
            gdst[slot] = (unsigned)(adj[k] + slot);
        }
    }
    __syncthreads();

    // Flush: run-coalesced flat copies; incremental (c, j) avoids per-elem division.
    unsigned long long orderBase =
        7ull * (unsigned long long)N + 2ull * (unsigned long long)nt2;
    if (valid == CHUNK) {
        int c = tid % 7;
        int j = tid / 7;
        #pragma unroll
        for (int r = 0; r < CHUNK * 7 / BLK; r++) {       // 28 iterations
            out[(unsigned long long)gdst[j] * 7ull + c] = stage[c * PITCH + j];
            int cn = c + 4;                               // 256 = 7*36 + 4
            bool wrap = (cn >= 7);
            c = wrap ? cn - 7 : cn;
            j += wrap ? 37 : 36;
        }
        #pragma unroll
        for (int r = 0; r < CHUNK / BLK; r++) {
            int i = r * BLK + tid;
            out[orderBase + gdst[i]] = stage[7 * PITCH + i];
        }
    } else {
        int totF = valid * 7;
        for (int i = tid; i < totF; i += BLK) {
            int j = i / 7;
            int c = i - 7 * j;
            out[(unsigned long long)gdst[j] * 7ull + c] = stage[c * PITCH + j];
        }
        for (int i = tid; i < valid; i += BLK)
            out[orderBase + gdst[i]] = stage[7 * PITCH + i];
    }
}

extern "C" void kernel_launch(void* const* d_in, const int* in_sizes, int n_in,
                              void* d_out, int out_size) {
    const float2* pos  = (const float2*)d_in[0];
    const float4* cov  = (const float4*)d_in[1];
    const float*  op   = (const float*)d_in[2];
    const int*    pnum = (const int*)d_in[3];
    int N = in_sizes[0] / 2;
    int nblk = (N + CHUNK - 1) / CHUNK;
    float* out = (float*)d_out;

    k_hist<<<nblk, BLK>>>(pos, pnum, N, nblk);
    k_scan<<<NBIN, BLK>>>(pnum, N, nblk, out);
    k_sort<<<nblk, BLK>>>(pos, cov, op, pnum, N, nblk, out);
}

// round 9
// speedup vs baseline: 2.1628x; 1.0394x over previous
#include <cuda_runtime.h>
#include <stdint.h>

// Stable counting sort by tile_id (<=256 bins), direct-to-output:
//  k_hist : tile id (uchar2) + per-block 256-bin histogram, float4-vectorized
//  k_scan : per-bin exclusive scan across blocks (uint4 rows) -> g_baseB, counts
//  k_sort : stable warp ranks (registers) -> chunk staged LOCALLY SORTED in shared
//           (SoA planes, conflict-free pitch); packed u64 shuffle-scan gives local
//           starts AND tile_offsets; run-coalesced flat flush straight to out.

#define NBIN    256
#define BLK     256
#define NW      8
#define ROUNDS  4
#define WSEG    (ROUNDS * 32)                     // 128 pts per warp
#define CHUNK   (NW * WSEG)                       // 1024 pts per block
#define PITCH   (CHUNK + 5)                       // pitch%32==5 -> conflict-free flush
#define MAXN    2000000
#define MAXBLK  ((MAXN + CHUNK - 1) / CHUNK)      // 1954
#define HSTRIDE 2048                              // padded row stride (16B aligned)

__device__ unsigned char g_tile8[MAXN + 2];
__device__ unsigned int  g_histB[NBIN * HSTRIDE];
__device__ unsigned int  g_baseB[NBIN * HSTRIDE];
__device__ unsigned int  g_counts[NBIN];

// ---------------- tile id + per-block histogram (vectorized) ----------------
__global__ void __launch_bounds__(BLK) k_hist(const float4* __restrict__ pos4,
                                              const int* __restrict__ pnum,
                                              int N) {
    __shared__ unsigned int cnt[NBIN];
    int tid = threadIdx.x;
    cnt[tid] = 0u;
    __syncthreads();
    int nt = *pnum;
    float inv_ts = (float)nt / 1024.0f;     // exact for power-of-two tile size
    int base4 = blockIdx.x * (CHUNK / 2);
    #pragma unroll
    for (int r = 0; r < CHUNK / 2 / BLK; r++) {   // 2 rounds, 2 pts each
        int i4 = base4 + r * BLK + tid;
        int p0 = 2 * i4;
        if (p0 + 1 < N) {
            float4 v = pos4[i4];
            int tx0 = min(max((int)(v.x * inv_ts), 0), nt - 1);
            int ty0 = min(max((int)(v.y * inv_ts), 0), nt - 1);
            int tx1 = min(max((int)(v.z * inv_ts), 0), nt - 1);
            int ty1 = min(max((int)(v.w * inv_ts), 0), nt - 1);
            int k0 = ty0 * nt + tx0;
            int k1 = ty1 * nt + tx1;
            ((uchar2*)g_tile8)[i4] = make_uchar2((unsigned char)k0, (unsigned char)k1);
            atomicAdd(&cnt[k0], 1u);
            atomicAdd(&cnt[k1], 1u);
        } else if (p0 < N) {
            float4 v = pos4[i4];
            int tx0 = min(max((int)(v.x * inv_ts), 0), nt - 1);
            int ty0 = min(max((int)(v.y * inv_ts), 0), nt - 1);
            int k0 = ty0 * nt + tx0;
            g_tile8[p0] = (unsigned char)k0;
            atomicAdd(&cnt[k0], 1u);
        }
    }
    __syncthreads();
    g_histB[tid * HSTRIDE + blockIdx.x] = cnt[tid];
}

// ---------------- per-bin exclusive scan across blocks (uint4 rows) ----------------
__global__ void __launch_bounds__(BLK) k_scan(const int* __restrict__ pnum,
                                              int N, int nblk,
                                              float* __restrict__ out) {
    int bin = blockIdx.x;
    int tid = threadIdx.x;
    unsigned base = (unsigned)bin * HSTRIDE + tid * 8u;
    uint4 A = *(const uint4*)&g_histB[base];
    uint4 B = *(const uint4*)&g_histB[base + 4];
    unsigned v[8] = {A.x, A.y, A.z, A.w, B.x, B.y, B.z, B.w};
    unsigned s = 0;
    #pragma unroll
    for (int j = 0; j < 8; j++) {
        if ((int)(tid * 8 + j) >= nblk) v[j] = 0u;
        s += v[j];
    }
    __shared__ unsigned int sh[BLK];
    sh[tid] = s;
    __syncthreads();
    for (int off = 1; off < BLK; off <<= 1) {
        unsigned int x = (tid >= off) ? sh[tid - off] : 0u;
        __syncthreads();
        sh[tid] += x;
        __syncthreads();
    }
    unsigned run = sh[tid] - s;
    unsigned o[8];
    #pragma unroll
    for (int j = 0; j < 8; j++) { o[j] = run; run += v[j]; }
    *(uint4*)&g_baseB[base]     = make_uint4(o[0], o[1], o[2], o[3]);
    *(uint4*)&g_baseB[base + 4] = make_uint4(o[4], o[5], o[6], o[7]);
    if (tid == BLK - 1) {
        g_counts[bin] = sh[BLK - 1];
        int nt2 = (*pnum) * (*pnum);
        if (bin < nt2)
            out[7ull * (unsigned long long)N + bin] = (float)sh[BLK - 1];
    }
}

// ------- rank + feature math + local-sort staging + run-coalesced output -------
__global__ void __launch_bounds__(BLK) k_sort(
    const float2* __restrict__ pos, const float4* __restrict__ cov,
    const float* __restrict__ opac, const int* __restrict__ pnum,
    int N, float* __restrict__ out)
{
    __shared__ float          stage[8 * PITCH];     // ~33KB SoA planes (7 feat + p)
    __shared__ unsigned int   gdst[CHUNK];          // 4KB global record idx per slot
    __shared__ unsigned short wcnt[NW * NBIN];      // 4KB counters -> warp prefix
    __shared__ unsigned short sbinstart[NBIN];
    __shared__ int            adj[NBIN];
    __shared__ unsigned long long wsum[NW];

    int tid  = threadIdx.x;
    int lane = tid & 31;
    int warp = tid >> 5;
    unsigned lt = (1u << lane) - 1u;
    int blk = blockIdx.x;
    int chunkStart = blk * CHUNK;
    int valid = min(CHUNK, N - chunkStart);
    int nt2;
    {
        int nt = *pnum;
        nt2 = nt * nt;
    }

    #pragma unroll
    for (int i = 0; i < NW * NBIN / 2 / BLK; i++)
        ((uint32_t*)wcnt)[i * BLK + tid] = 0u;
    __syncthreads();

    // Phase A: stable within-warp ranks (registers)
    unsigned short* mycnt = &wcnt[warp * NBIN];
    unsigned packed[ROUNDS];
    #pragma unroll
    for (int r = 0; r < ROUNDS; r++) {
        int local = warp * WSEG + r * 32 + lane;
        int p = chunkStart + local;
        int k = (p < N) ? (int)g_tile8[p] : 300;
        unsigned mask = __match_any_sync(0xffffffffu, k);
        int leader = __ffs(mask) - 1;
        int rank_w = __popc(mask & lt);
        unsigned base = 0u;
        if (lane == leader && k < 256) {
            base = (unsigned)mycnt[k];
            mycnt[k] = (unsigned short)(base + (unsigned)__popc(mask));
        }
        base = __shfl_sync(0xffffffffu, base, leader);
        packed[r] = ((base + (unsigned)rank_w) << 16) | (unsigned)(k & 0xffff);
    }
    __syncthreads();

    // Combine: warp prefix per bin; packed u64 shuffle-scan:
    //   lo = exscan(g_counts) = tile_offsets, hi = exscan(local totals) = starts.
    unsigned loc;
    {
        unsigned s = 0u;
        #pragma unroll
        for (int w = 0; w < NW; w++) {
            unsigned c = (unsigned)wcnt[w * NBIN + tid];
            wcnt[w * NBIN + tid] = (unsigned short)s;
            s += c;
        }
        loc = s;
    }
    unsigned cntg = g_counts[tid];
    unsigned long long v64 = ((unsigned long long)loc << 32) | (unsigned long long)cntg;
    unsigned long long x = v64;
    #pragma unroll
    for (int d = 1; d < 32; d <<= 1) {
        unsigned long long y = __shfl_up_sync(0xffffffffu, x, d);
        if (lane >= d) x += y;
    }
    if (lane == 31) wsum[warp] = x;
    __syncthreads();
    if (warp == 0) {
        unsigned long long t = (lane < NW) ? wsum[lane] : 0ull;
        #pragma unroll
        for (int d = 1; d < NW; d <<= 1) {
            unsigned long long y = __shfl_up_sync(0xffffffffu, t, d);
            if (lane >= d) t += y;
        }
        if (lane < NW) wsum[lane] = t;
    }
    __syncthreads();
    {
        unsigned long long incl = x + (warp ? wsum[warp - 1] : 0ull);
        unsigned long long excl = incl - v64;
        unsigned offs = (unsigned)excl;
        unsigned bs   = (unsigned)(excl >> 32);
        sbinstart[tid] = (unsigned short)bs;
        adj[tid] = (int)(offs + g_baseB[tid * HSTRIDE + blk]) - (int)bs;
        if (blk == 0 && tid < nt2)
            out[7ull * (unsigned long long)N + nt2 + tid] = (float)offs;
    }
    __syncthreads();

    // Phase C: coalesced reads + math -> stage at locally-sorted slot
    #pragma unroll
    for (int r = 0; r < ROUNDS; r++) {
        int local = warp * WSEG + r * 32 + lane;
        int p = chunkStart + local;
        if (p < N) {
            int k = (int)(packed[r] & 0xffffu);
            int slot = (int)sbinstart[k] + (int)mycnt[k] + (int)(packed[r] >> 16);

            float2 xy = pos[p];
            float4 cv = cov[p];
            float op  = opac[p];
            float a = cv.x, b = cv.y, c = cv.z, d = cv.w;
            float trace = a + d;
            float det   = a * d - b * c;
            float t1 = 0.5f * trace;
            float disc = trace * trace - 4.0f * det;
            float t2 = 0.5f * sqrtf(fmaxf(disc, 0.0f));
            float radius = fmaxf(t1 - t2, t1 + t2);
            float inv = 1.0f / det;

            stage[0 * PITCH + slot] = xy.x;
            stage[1 * PITCH + slot] = xy.y;
            stage[2 * PITCH + slot] = d * inv;
            stage[3 * PITCH + slot] = -b * inv;
            stage[4 * PITCH + slot] = a * inv;
            stage[5 * PITCH + slot] = op;
            stage[6 * PITCH + slot] = radius;
            stage[7 * PITCH + slot] = (float)p;
            gdst[slot] = (unsigned)(adj[k] + slot);
        }
    }
    __syncthreads();

    // Flush: run-coalesced flat copies; unsigned 32-bit offset math.
    unsigned long long orderBase =
        7ull * (unsigned long long)N + 2ull * (unsigned long long)nt2;
    if (valid == CHUNK) {
        int c = tid % 7;
        int j = tid / 7;
        #pragma unroll
        for (int r = 0; r < CHUNK * 7 / BLK; r++) {       // 28 iterations
            unsigned dst = gdst[j] * 7u + (unsigned)c;
            out[dst] = stage[c * PITCH + j];
            int cn = c + 4;                               // 256 = 7*36 + 4
            bool wrap = (cn >= 7);
            c = wrap ? cn - 7 : cn;
            j += wrap ? 37 : 36;
        }
        #pragma unroll
        for (int r = 0; r < CHUNK / BLK; r++) {
            int i = r * BLK + tid;
            out[orderBase + gdst[i]] = stage[7 * PITCH + i];
        }
    } else {
        int totF = valid * 7;
        for (int i = tid; i < totF; i += BLK) {
            int j = i / 7;
            int c = i - 7 * j;
            out[gdst[j] * 7u + (unsigned)c] = stage[c * PITCH + j];
        }
        for (int i = tid; i < valid; i += BLK)
            out[orderBase + gdst[i]] = stage[7 * PITCH + i];
    }
}

extern "C" void kernel_launch(void* const* d_in, const int* in_sizes, int n_in,
                              void* d_out, int out_size) {
    const float4* pos4 = (const float4*)d_in[0];
    const float2* pos  = (const float2*)d_in[0];
    const float4* cov  = (const float4*)d_in[1];
    const float*  op   = (const float*)d_in[2];
    const int*    pnum = (const int*)d_in[3];
    int N = in_sizes[0] / 2;
    int nblk = (N + CHUNK - 1) / CHUNK;
    float* out = (float*)d_out;

    k_hist<<<nblk, BLK>>>(pos4, pnum, N);
    k_scan<<<NBIN, BLK>>>(pnum, N, nblk, out);
    k_sort<<<nblk, BLK>>>(pos, cov, op, pnum, N, out);
}